// round 1
// baseline (speedup 1.0000x reference)
#include <cuda_runtime.h>

// WavePool3D: 3D Haar wavelet pooling, kernel=stride=2.
// Input  x: [1, 32, 128, 128, 128] fp32 (W contiguous)
// Output  : [8, 1, 32, 64, 64, 64] fp32 (8 subbands LLL..HHH, contiguous)
//
// Each thread: one (c, d, h, wq) where wq indexes a group of 4 input W
// elements (= 2 output w positions). Loads 4x float4 (the 2x2 D/H rows),
// does the 3-axis Haar butterfly, stores 8x float2 (one per subband).
// Pure streaming: 64B in, 64B out per thread, fully coalesced.

#define C_DIM   32
#define DO_DIM  64   // output depth
#define HO_DIM  64
#define WO_DIM  64
#define WQ_DIM  32   // WO_DIM / 2 (each thread handles 2 output w)

#define IN_W    128
#define IN_HW   (128 * 128)
#define IN_DHW  (128 * 128 * 128)

#define OUT_W   64
#define OUT_HW  (64 * 64)
#define OUT_DHW (64 * 64 * 64)
#define OUT_CDHW (C_DIM * OUT_DHW)   // stride between subbands

__global__ __launch_bounds__(256)
void wavepool3d_kernel(const float* __restrict__ x, float* __restrict__ out)
{
    unsigned idx = blockIdx.x * blockDim.x + threadIdx.x;
    // idx layout: [c:5][d:6][h:6][wq:5]  -> wq fastest for coalescing
    unsigned wq = idx & 31u;
    unsigned h  = (idx >> 5) & 63u;
    unsigned d  = (idx >> 11) & 63u;
    unsigned c  = idx >> 17;

    // Input base: x[c][2d + i][2h + j][4*wq + 0..3]
    const float* base = x + (size_t)c * IN_DHW
                          + (size_t)(2u * d) * IN_HW
                          + (size_t)(2u * h) * IN_W
                          + 4u * wq;

    // rows: a{i}{j} = 4 consecutive W values at (D=2d+i, H=2h+j)
    float4 a00 = *reinterpret_cast<const float4*>(base);
    float4 a01 = *reinterpret_cast<const float4*>(base + IN_W);
    float4 a10 = *reinterpret_cast<const float4*>(base + IN_HW);
    float4 a11 = *reinterpret_cast<const float4*>(base + IN_HW + IN_W);

    const float scale = 0.35355339059327378f;  // 1/(2*sqrt(2))

    float2 r[8];  // r[f].x = output w pos 2*wq, .y = 2*wq+1

    #pragma unroll
    for (int p = 0; p < 2; p++) {
        // k-axis (W) butterfly: e = s0+s1, o = s1-s0 per (i,j) row
        float s00_0 = p ? a00.z : a00.x, s00_1 = p ? a00.w : a00.y;
        float s01_0 = p ? a01.z : a01.x, s01_1 = p ? a01.w : a01.y;
        float s10_0 = p ? a10.z : a10.x, s10_1 = p ? a10.w : a10.y;
        float s11_0 = p ? a11.z : a11.x, s11_1 = p ? a11.w : a11.y;

        float e00 = s00_0 + s00_1, o00 = s00_1 - s00_0;
        float e01 = s01_0 + s01_1, o01 = s01_1 - s01_0;
        float e10 = s10_0 + s10_1, o10 = s10_1 - s10_0;
        float e11 = s11_0 + s11_1, o11 = s11_1 - s11_0;

        // j-axis (H): L = sum over j, H = (j=1) - (j=0)
        float le0 = e00 + e01, he0 = e01 - e00;
        float le1 = e10 + e11, he1 = e11 - e10;
        float lo0 = o00 + o01, ho0 = o01 - o00;
        float lo1 = o10 + o11, ho1 = o11 - o10;

        // i-axis (D): L = sum over i, H = (i=1) - (i=0)
        float f0 = (le0 + le1) * scale;   // LLL
        float f1 = (lo0 + lo1) * scale;   // LLH
        float f2 = (he0 + he1) * scale;   // LHL
        float f3 = (ho0 + ho1) * scale;   // LHH
        float f4 = (le1 - le0) * scale;   // HLL
        float f5 = (lo1 - lo0) * scale;   // HLH
        float f6 = (he1 - he0) * scale;   // HHL
        float f7 = (ho1 - ho0) * scale;   // HHH

        if (p == 0) {
            r[0].x = f0; r[1].x = f1; r[2].x = f2; r[3].x = f3;
            r[4].x = f4; r[5].x = f5; r[6].x = f6; r[7].x = f7;
        } else {
            r[0].y = f0; r[1].y = f1; r[2].y = f2; r[3].y = f3;
            r[4].y = f4; r[5].y = f5; r[6].y = f6; r[7].y = f7;
        }
    }

    // out[f][c][d][h][2*wq .. 2*wq+1]
    float* obase = out + (size_t)c * OUT_DHW
                       + (size_t)d * OUT_HW
                       + (size_t)h * OUT_W
                       + 2u * wq;
    #pragma unroll
    for (int f = 0; f < 8; f++) {
        *reinterpret_cast<float2*>(obase + (size_t)f * OUT_CDHW) = r[f];
    }
}

extern "C" void kernel_launch(void* const* d_in, const int* in_sizes, int n_in,
                              void* d_out, int out_size)
{
    const float* x = (const float*)d_in[0];
    float* out = (float*)d_out;

    // total threads = 32 * 64 * 64 * 32 = 4,194,304
    const unsigned total = C_DIM * DO_DIM * HO_DIM * WQ_DIM;
    const unsigned block = 256;
    wavepool3d_kernel<<<total / block, block>>>(x, out);
}